// round 4
// baseline (speedup 1.0000x reference)
#include <cuda_runtime.h>
#include <math.h>
#include <stdint.h>

// Problem constants
#define LEVEL   16
#define LENGTH  64
#define TOPK    2
#define SIZE    512
#define BATCH   32
#define NEG     (-1e8f)

#define LPOS    48              // LENGTH - LEVEL
#define NCELLS  904
#define NIDX    768             // LPOS * LEVEL
#define ROWS1   49152           // K*B*LPOS*LEVEL  (GEMM1 rows)
#define ROWS2   3072            // B*LPOS*K        (GEMM2 rows)
#define KSPLIT  4
#define NCELLS_BL 1536          // BATCH*LPOS
#define MAXCAND 16
#define MAXR    (NCELLS_BL * MAXCAND)
#define GUARD   0.02f

// Output layout (float32, concatenated in reference return order)
#define OFF_H   0
#define OFF_S   1572864         // 3072*512
#define OFF_N   1575936
#define OFF_LK  1579008
#define OFF_RK  1582080

// Scratch (static device globals: allocation-free per harness rules)
__device__ float g_U[(size_t)ROWS1 * 512];              // ~100.7 MB (3xTF32 ~ fp32)
__device__ float g_P[(size_t)KSPLIT * ROWS2 * 512];     // ~25 MB split-K partials
__device__ int   g_li[NIDX];
__device__ int   g_ri[NIDX];
__device__ int4  g_sel[ROWS2];
__device__ int   g_nrows;
__device__ int   g_rows[MAXR];          // (bl<<6)|z
__device__ float g_sexact[MAXR];
__device__ int   g_cellbase[NCELLS_BL];
__device__ int   g_cellcnt[NCELLS_BL];
__device__ int   g_cellflag[NCELLS_BL];

typedef unsigned long long u64t;

// packed f32x2 FMA: acc = a*b + acc (2 lanes per instruction)
#define FFMA2(acc, a, b) \
    asm("fma.rn.f32x2 %0, %1, %2, %0;" : "+l"(acc) : "l"(a), "l"(b))

__device__ __forceinline__ void mma_tf32(float d[4],
        uint32_t a0, uint32_t a1, uint32_t a2, uint32_t a3,
        uint32_t b0, uint32_t b1) {
    asm volatile(
        "mma.sync.aligned.m16n8k8.row.col.f32.tf32.tf32.f32 "
        "{%0,%1,%2,%3}, {%4,%5,%6,%7}, {%8,%9}, {%0,%1,%2,%3};"
        : "+f"(d[0]), "+f"(d[1]), "+f"(d[2]), "+f"(d[3])
        : "r"(a0), "r"(a1), "r"(a2), "r"(a3), "r"(b0), "r"(b1));
}

__device__ __forceinline__ float tf32_rna(float x) {
    uint32_t u;
    asm("cvt.rna.tf32.f32 %0, %1;" : "=r"(u) : "f"(x));
    return __uint_as_float(u);
}

// ---------------------------------------------------------------------------
// K0: index conversion + counter reset.
__global__ void conv_idx_kernel(const void* __restrict__ lraw,
                                const void* __restrict__ rraw) {
    if (blockIdx.x == 0 && threadIdx.x == 0) g_nrows = 0;
    const int* w = (const int*)lraw;
    bool is64 = (w[1] == 0 && w[2] == 64);
    int t = blockIdx.x * blockDim.x + threadIdx.x;
    if (t < NIDX) {
        if (is64) {
            g_li[t] = (int)((const long long*)lraw)[t];
            g_ri[t] = (int)((const long long*)rraw)[t];
        } else {
            g_li[t] = ((const int*)lraw)[t];
            g_ri[t] = ((const int*)rraw)[t];
        }
    }
}

// ---------------------------------------------------------------------------
// K1: U = gather(chart_h left cells) @ mat via 3xTF32 mma (fp32-level accuracy).
// Block: 128x128 tile, BK=16, 256 thr = 8 warps (2x4), warp tile 64x32.
__global__ __launch_bounds__(256) void gemm1_3x_kernel(
    const float* __restrict__ chart_h, const float* __restrict__ mat) {
    __shared__ float AsH[128][20];
    __shared__ float AsL[128][20];
    __shared__ float BsH[16][132];
    __shared__ float BsL[16][132];
    __shared__ const float* Arow[128];

    int tid  = threadIdx.x;
    int row0 = blockIdx.y * 128;
    int col0 = blockIdx.x * 128;

    if (tid < 128) {
        int r = row0 + tid;
        int k = r & 1;
        int t = r >> 1;
        int n = t & 15;
        int bl = t >> 4;
        int l = bl % LPOS, b = bl / LPOS;
        int cell = g_li[(l << 4) + n];
        Arow[tid] = chart_h + (((size_t)(k * BATCH + b)) * NCELLS + cell) * SIZE;
    }
    __syncthreads();

    int wid = tid >> 5, lane = tid & 31;
    int wm = wid >> 2, wn = wid & 3;          // warp grid 2(M) x 4(N)
    int gid = lane >> 2, tig = lane & 3;

    float d[4][4][4];
#pragma unroll
    for (int mf = 0; mf < 4; mf++)
#pragma unroll
        for (int nf = 0; nf < 4; nf++)
#pragma unroll
            for (int c = 0; c < 4; c++) d[mf][nf][c] = 0.f;

    int ar = tid >> 1, ac = (tid & 1) * 8;    // A: 2 thr/row, 8 floats each
    int br = tid >> 4, bc = (tid & 15) * 8;   // B: 16 thr/row, 8 floats each

    for (int kt = 0; kt < 32; kt++) {
        int kb = kt * 16;
        float4 av0 = *(const float4*)(Arow[ar] + kb + ac);
        float4 av1 = *(const float4*)(Arow[ar] + kb + ac + 4);
        float4 bv0 = *(const float4*)(mat + (size_t)(kb + br) * 512 + col0 + bc);
        float4 bv1 = *(const float4*)(mat + (size_t)(kb + br) * 512 + col0 + bc + 4);
        __syncthreads();
        {
            float a[8] = {av0.x, av0.y, av0.z, av0.w, av1.x, av1.y, av1.z, av1.w};
            float b[8] = {bv0.x, bv0.y, bv0.z, bv0.w, bv1.x, bv1.y, bv1.z, bv1.w};
#pragma unroll
            for (int j = 0; j < 8; j++) {
                float ah = tf32_rna(a[j]);
                AsH[ar][ac + j] = ah;
                AsL[ar][ac + j] = tf32_rna(a[j] - ah);
                float bh = tf32_rna(b[j]);
                BsH[br][bc + j] = bh;
                BsL[br][bc + j] = tf32_rna(b[j] - bh);
            }
        }
        __syncthreads();
#pragma unroll
        for (int kf = 0; kf < 2; kf++) {
            int k0 = kf * 8;
            uint32_t aH[4][4], aL[4][4], bH[4][2], bL[4][2];
#pragma unroll
            for (int mf = 0; mf < 4; mf++) {
                int m = wm * 64 + mf * 16 + gid;
                aH[mf][0] = __float_as_uint(AsH[m][k0 + tig]);
                aH[mf][1] = __float_as_uint(AsH[m + 8][k0 + tig]);
                aH[mf][2] = __float_as_uint(AsH[m][k0 + tig + 4]);
                aH[mf][3] = __float_as_uint(AsH[m + 8][k0 + tig + 4]);
                aL[mf][0] = __float_as_uint(AsL[m][k0 + tig]);
                aL[mf][1] = __float_as_uint(AsL[m + 8][k0 + tig]);
                aL[mf][2] = __float_as_uint(AsL[m][k0 + tig + 4]);
                aL[mf][3] = __float_as_uint(AsL[m + 8][k0 + tig + 4]);
            }
#pragma unroll
            for (int nf = 0; nf < 4; nf++) {
                int nn = wn * 32 + nf * 8 + gid;
                bH[nf][0] = __float_as_uint(BsH[k0 + tig][nn]);
                bH[nf][1] = __float_as_uint(BsH[k0 + tig + 4][nn]);
                bL[nf][0] = __float_as_uint(BsL[k0 + tig][nn]);
                bL[nf][1] = __float_as_uint(BsL[k0 + tig + 4][nn]);
            }
#pragma unroll
            for (int mf = 0; mf < 4; mf++)
#pragma unroll
                for (int nf = 0; nf < 4; nf++) {
                    mma_tf32(d[mf][nf], aH[mf][0], aH[mf][1], aH[mf][2], aH[mf][3],
                             bL[nf][0], bL[nf][1]);
                    mma_tf32(d[mf][nf], aL[mf][0], aL[mf][1], aL[mf][2], aL[mf][3],
                             bH[nf][0], bH[nf][1]);
                    mma_tf32(d[mf][nf], aH[mf][0], aH[mf][1], aH[mf][2], aH[mf][3],
                             bH[nf][0], bH[nf][1]);
                }
        }
    }
#pragma unroll
    for (int mf = 0; mf < 4; mf++) {
        int rA = row0 + wm * 64 + mf * 16 + gid;
#pragma unroll
        for (int nf = 0; nf < 4; nf++) {
            int cA = col0 + wn * 32 + nf * 8 + tig * 2;
            *(float2*)(g_U + (size_t)rA * 512 + cA)       = make_float2(d[mf][nf][0], d[mf][nf][1]);
            *(float2*)(g_U + (size_t)(rA + 8) * 512 + cA) = make_float2(d[mf][nf][2], d[mf][nf][3]);
        }
    }
}

// ---------------------------------------------------------------------------
// K2: scores + top-2. If margin comfortable: write outputs directly.
// If near-tie (< GUARD): nominate candidates for exact fp32 rescore.
__global__ __launch_bounds__(256) void score_topk_kernel(
    const float* __restrict__ chart_h, const float* __restrict__ chart_s,
    float* __restrict__ out) {
    int bl = blockIdx.x;                 // 0..1535
    int b = bl / LPOS, l = bl % LPOS;
    int warp = threadIdx.x >> 5;
    int lane = threadIdx.x & 31;

    __shared__ float s[64];

    for (int n = warp; n < 16; n += 8) {
        int lcell = g_li[(l << 4) + n];
        int rcell = g_ri[(l << 4) + n];
        const float4* u0 = (const float4*)(g_U + ((((size_t)bl * 16) + n) * 2 + 0) * 512);
        const float4* u1 = u0 + 128;
        const float4* r0 = (const float4*)(chart_h + (((size_t)b) * NCELLS + rcell) * SIZE);
        const float4* r1 = (const float4*)(chart_h + (((size_t)(BATCH + b)) * NCELLS + rcell) * SIZE);
        float a00 = 0.f, a01 = 0.f, a10 = 0.f, a11 = 0.f;
#pragma unroll
        for (int it = 0; it < 4; it++) {
            int i = lane + it * 32;
            float4 x0 = u0[i], x1 = u1[i], y0 = r0[i], y1 = r1[i];
            a00 += x0.x*y0.x + x0.y*y0.y + x0.z*y0.z + x0.w*y0.w;
            a01 += x0.x*y1.x + x0.y*y1.y + x0.z*y1.z + x0.w*y1.w;
            a10 += x1.x*y0.x + x1.y*y0.y + x1.z*y0.z + x1.w*y0.w;
            a11 += x1.x*y1.x + x1.y*y1.y + x1.z*y1.z + x1.w*y1.w;
        }
#pragma unroll
        for (int o = 16; o; o >>= 1) {
            a00 += __shfl_xor_sync(0xffffffffu, a00, o);
            a01 += __shfl_xor_sync(0xffffffffu, a01, o);
            a10 += __shfl_xor_sync(0xffffffffu, a10, o);
            a11 += __shfl_xor_sync(0xffffffffu, a11, o);
        }
        if (lane == 0) {
            float ls0 = chart_s[(size_t)b * NCELLS + lcell];
            float ls1 = chart_s[(size_t)(BATCH + b) * NCELLS + lcell];
            float rs0 = chart_s[(size_t)b * NCELLS + rcell];
            float rs1 = chart_s[(size_t)(BATCH + b) * NCELLS + rcell];
            float v00 = a00 + ls0 + rs0, v01 = a01 + ls0 + rs1;
            float v10 = a10 + ls1 + rs0, v11 = a11 + ls1 + rs1;
            if (n == 0) { v10 = NEG; v11 = NEG; }   // penalty: catalan(1)=1
            s[n * 4 + 0] = v00; s[n * 4 + 1] = v01;
            s[n * 4 + 2] = v10; s[n * 4 + 3] = v11;
        }
    }
    __syncthreads();

    if (threadIdx.x == 0) {
        float b1 = -INFINITY; int i1 = 0;
        for (int z = 0; z < 64; z++) { float v = s[z]; if (v > b1) { b1 = v; i1 = z; } }
        float b2 = -INFINITY; int i2 = 0;
        for (int z = 0; z < 64; z++) {
            if (z == i1) continue;
            float v = s[z]; if (v > b2) { b2 = v; i2 = z; }
        }
        float b3 = -INFINITY;
        for (int z = 0; z < 64; z++) {
            if (z == i1 || z == i2) continue;
            float v = s[z]; if (v > b3) b3 = v;
        }
        float m1 = b1 - b2, m2 = b2 - b3;
        if (m1 < GUARD || m2 < GUARD) {
            // near-tie: nominate everything within GUARD of b2 for exact rescore
            int cand[MAXCAND];
            int cnt = 0;
            cand[cnt++] = i1;
            cand[cnt++] = i2;
            float thr = b2 - GUARD;
            for (int z = 0; z < 64 && cnt < MAXCAND; z++) {
                if (z == i1 || z == i2) continue;
                if (s[z] >= thr) cand[cnt++] = z;
            }
            int base = atomicAdd(&g_nrows, cnt);
            g_cellbase[bl] = base;
            g_cellcnt[bl]  = cnt;
            g_cellflag[bl] = 1;
            for (int c = 0; c < cnt; c++) g_rows[base + c] = (bl << 6) | cand[c];
        } else {
            g_cellflag[bl] = 0;
            int o = bl * 2;
            out[OFF_S  + o]     = b1;
            out[OFF_S  + o + 1] = b2;
            out[OFF_N  + o]     = (float)(i1 >> 2);
            out[OFF_N  + o + 1] = (float)(i2 >> 2);
            out[OFF_LK + o]     = (float)((i1 >> 1) & 1);
            out[OFF_LK + o + 1] = (float)((i2 >> 1) & 1);
            out[OFF_RK + o]     = (float)(i1 & 1);
            out[OFF_RK + o + 1] = (float)(i2 & 1);
            g_sel[o]     = make_int4(i1 >> 2, (i1 >> 1) & 1, i1 & 1, 0);
            g_sel[o + 1] = make_int4(i2 >> 2, (i2 >> 1) & 1, i2 & 1, 0);
        }
    }
}

// ---------------------------------------------------------------------------
// K3: exact fp32 rescore for the (rare) near-tie candidates.
// s = (lh @ mat) . rh + ls + rs. One block per candidate, grid-stride.
__global__ __launch_bounds__(256) void rescore_exact_kernel(
    const float* __restrict__ chart_h, const float* __restrict__ chart_s,
    const float* __restrict__ mat) {
    __shared__ float lh_s[512];
    __shared__ float red[8];
    int nrows = g_nrows;
    int t = threadIdx.x;

    for (int r = blockIdx.x; r < nrows; r += gridDim.x) {
        int code = g_rows[r];
        int bl = code >> 6, z = code & 63;
        int n = z >> 2, kl = (z >> 1) & 1, kr = z & 1;
        int b = bl / LPOS, l = bl % LPOS;
        int lcell = g_li[(l << 4) + n];
        int rcell = g_ri[(l << 4) + n];
        const float* lh = chart_h + (((size_t)(kl * BATCH + b)) * NCELLS + lcell) * SIZE;
        const float* rh = chart_h + (((size_t)(kr * BATCH + b)) * NCELLS + rcell) * SIZE;
        __syncthreads();
        lh_s[t] = lh[t];
        lh_s[t + 256] = lh[t + 256];
        __syncthreads();
        float u0 = 0.f, u1 = 0.f;
        for (int i = 0; i < 512; i++) {
            float a = lh_s[i];
            u0 += a * mat[(size_t)i * 512 + t];
            u1 += a * mat[(size_t)i * 512 + t + 256];
        }
        float part = u0 * rh[t] + u1 * rh[t + 256];
#pragma unroll
        for (int o = 16; o; o >>= 1) part += __shfl_xor_sync(0xffffffffu, part, o);
        if ((t & 31) == 0) red[t >> 5] = part;
        __syncthreads();
        if (t == 0) {
            float x = 0.f;
#pragma unroll
            for (int i = 0; i < 8; i++) x += red[i];
            float ls = chart_s[(size_t)(kl * BATCH + b) * NCELLS + lcell];
            float rs = chart_s[(size_t)(kr * BATCH + b) * NCELLS + rcell];
            g_sexact[r] = x + ls + rs;
        }
    }
}

// ---------------------------------------------------------------------------
// K4: for flagged cells, select exact top-2 and overwrite outputs + g_sel.
__global__ __launch_bounds__(256) void fix_select_kernel(float* __restrict__ out) {
    int bl = blockIdx.x * 256 + threadIdx.x;
    if (bl >= NCELLS_BL) return;
    if (!g_cellflag[bl]) return;
    int base = g_cellbase[bl];
    int cnt  = g_cellcnt[bl];

    float s1 = -INFINITY, s2 = -INFINITY;
    int z1 = 64, z2 = 64;
    for (int c = 0; c < cnt; c++) {
        float v = g_sexact[base + c];
        int z = g_rows[base + c] & 63;
        if (v > s1 || (v == s1 && z < z1)) {
            s2 = s1; z2 = z1; s1 = v; z1 = z;
        } else if (v > s2 || (v == s2 && z < z2)) {
            s2 = v; z2 = z;
        }
    }
    int o = bl * 2;
    out[OFF_S  + o]     = s1;
    out[OFF_S  + o + 1] = s2;
    out[OFF_N  + o]     = (float)(z1 >> 2);
    out[OFF_N  + o + 1] = (float)(z2 >> 2);
    out[OFF_LK + o]     = (float)((z1 >> 1) & 1);
    out[OFF_LK + o + 1] = (float)((z2 >> 1) & 1);
    out[OFF_RK + o]     = (float)(z1 & 1);
    out[OFF_RK + o + 1] = (float)(z2 & 1);
    g_sel[o]     = make_int4(z1 >> 2, (z1 >> 1) & 1, z1 & 1, 0);
    g_sel[o + 1] = make_int4(z2 >> 2, (z2 >> 1) & 1, z2 & 1, 0);
}

// ---------------------------------------------------------------------------
// K5: split-K compose GEMM (FFMA2), partials -> g_P.
__global__ __launch_bounds__(256, 2) void gemm2_kernel(
    const float* __restrict__ chart_h, const float* __restrict__ Wc) {
    __shared__ float As2[16][256];
    __shared__ float Bs[16][128];
    __shared__ const float* Arow[128];

    int tid  = threadIdx.x;
    int row0 = blockIdx.y * 128;
    int col0 = blockIdx.x * 128;
    int ks   = blockIdx.z;
    int kbase = ks * 256;

    if (tid < 128) {
        int r = row0 + tid;
        int bl = r >> 1;
        int b = bl / LPOS, l = bl % LPOS;
        int4 sel = g_sel[r];
        const float* base;
        if (kbase < 512) {
            int lcell = g_li[(l << 4) + sel.x];
            base = chart_h + (((size_t)(sel.y * BATCH + b)) * NCELLS + lcell) * SIZE + kbase;
        } else {
            int rcell = g_ri[(l << 4) + sel.x];
            base = chart_h + (((size_t)(sel.z * BATCH + b)) * NCELLS + rcell) * SIZE + (kbase - 512);
        }
        Arow[tid] = base;
    }
    __syncthreads();

    u64t acc[8][4];
#pragma unroll
    for (int i = 0; i < 8; i++)
#pragma unroll
        for (int j = 0; j < 4; j++) acc[i][j] = 0ull;

    int arow  = tid >> 1;
    int ahalf = (tid & 1) * 8;
    int brow  = tid >> 5;
    int bcol4 = (tid & 31) * 4;
    int ty = tid >> 4, tx = tid & 15;

    for (int kk = 0; kk < 256; kk += 16) {
        float4 av0 = *(const float4*)(Arow[arow] + kk + ahalf);
        float4 av1 = *(const float4*)(Arow[arow] + kk + ahalf + 4);
        *(float2*)&As2[ahalf + 0][2 * arow] = make_float2(av0.x, av0.x);
        *(float2*)&As2[ahalf + 1][2 * arow] = make_float2(av0.y, av0.y);
        *(float2*)&As2[ahalf + 2][2 * arow] = make_float2(av0.z, av0.z);
        *(float2*)&As2[ahalf + 3][2 * arow] = make_float2(av0.w, av0.w);
        *(float2*)&As2[ahalf + 4][2 * arow] = make_float2(av1.x, av1.x);
        *(float2*)&As2[ahalf + 5][2 * arow] = make_float2(av1.y, av1.y);
        *(float2*)&As2[ahalf + 6][2 * arow] = make_float2(av1.z, av1.z);
        *(float2*)&As2[ahalf + 7][2 * arow] = make_float2(av1.w, av1.w);
        int kg = kbase + kk;
        *(float4*)(&Bs[brow][bcol4]) =
            *(const float4*)(Wc + (size_t)(kg + brow) * 512 + col0 + bcol4);
        *(float4*)(&Bs[brow + 8][bcol4]) =
            *(const float4*)(Wc + (size_t)(kg + brow + 8) * 512 + col0 + bcol4);
        __syncthreads();
#pragma unroll
        for (int kq = 0; kq < 16; kq++) {
            u64t a2[8], b2[4];
#pragma unroll
            for (int i = 0; i < 8; i++)
                a2[i] = *(const u64t*)&As2[kq][2 * (ty * 8 + i)];
#pragma unroll
            for (int j = 0; j < 4; j++)
                b2[j] = ((const u64t*)&Bs[kq][tx * 8])[j];
#pragma unroll
            for (int i = 0; i < 8; i++)
#pragma unroll
                for (int j = 0; j < 4; j++) FFMA2(acc[i][j], a2[i], b2[j]);
        }
        __syncthreads();
    }
#pragma unroll
    for (int i = 0; i < 8; i++) {
        int r = row0 + ty * 8 + i;
        u64t* crow = (u64t*)(g_P + ((size_t)ks * ROWS2 + r) * 512 + col0 + tx * 8);
#pragma unroll
        for (int j = 0; j < 4; j++) crow[j] = acc[i][j];
    }
}

// ---------------------------------------------------------------------------
// K6: combine split-K partials + bias + tanh + unit-norm, write topk_h.
__global__ __launch_bounds__(256) void combine_normalize_kernel(
    const float* __restrict__ bc, float* __restrict__ out) {
    int r = blockIdx.x;
    int t = threadIdx.x;
    const float* p = g_P + (size_t)r * 512;
    const size_t stride = (size_t)ROWS2 * 512;

    float v0 = bc[t]       + p[t]       + p[t + stride]       + p[t + 2*stride]       + p[t + 3*stride];
    float v1 = bc[t + 256] + p[t + 256] + p[t + 256 + stride] + p[t + 256 + 2*stride] + p[t + 256 + 3*stride];
    v0 = tanhf(v0);
    v1 = tanhf(v1);

    float ss = v0 * v0 + v1 * v1;
#pragma unroll
    for (int o = 16; o; o >>= 1) ss += __shfl_xor_sync(0xffffffffu, ss, o);
    __shared__ float red[8];
    __shared__ float s_inv;
    if ((t & 31) == 0) red[t >> 5] = ss;
    __syncthreads();
    if (t == 0) {
        float x = 0.f;
#pragma unroll
        for (int i = 0; i < 8; i++) x += red[i];
        s_inv = 1.0f / sqrtf(x);
    }
    __syncthreads();
    float inv = s_inv;
    out[OFF_H + (size_t)r * 512 + t]       = v0 * inv;
    out[OFF_H + (size_t)r * 512 + t + 256] = v1 * inv;
}

// ---------------------------------------------------------------------------
extern "C" void kernel_launch(void* const* d_in, const int* in_sizes, int n_in,
                              void* d_out, int out_size) {
    const float* chart_h = (const float*)d_in[0];
    const float* chart_s = (const float*)d_in[1];
    const void*  l_index = d_in[2];
    const void*  r_index = d_in[3];
    const float* mat     = (const float*)d_in[4];
    const float* Wc      = (const float*)d_in[5];
    const float* bc      = (const float*)d_in[6];
    float* out = (float*)d_out;

    conv_idx_kernel<<<3, 256>>>(l_index, r_index);
    gemm1_3x_kernel<<<dim3(4, ROWS1 / 128), 256>>>(chart_h, mat);
    score_topk_kernel<<<NCELLS_BL, 256>>>(chart_h, chart_s, out);
    rescore_exact_kernel<<<64, 256>>>(chart_h, chart_s, mat);
    fix_select_kernel<<<6, 256>>>(out);
    gemm2_kernel<<<dim3(4, ROWS2 / 128, KSPLIT), 256>>>(chart_h, Wc);
    combine_normalize_kernel<<<ROWS2, 256>>>(bc, out);
}